// round 15
// baseline (speedup 1.0000x reference)
#include <cuda_runtime.h>
#include <cuda_bf16.h>
#include <cstddef>
#include <cstdint>

// Problem constants
#define BATCH 8
#define SEQ   1024
#define CDIM  768
#define HEADS 24
#define DHEAD 32
#define QKV_N (3*CDIM)          // 2304
#define ROWS  (BATCH*SEQ)       // 8192

#define LOG2E 1.4426950408889634f

__device__ __forceinline__ uint32_t f2tf(float f) {
    uint32_t u; asm("cvt.rna.tf32.f32 %0,%1;" : "=r"(u) : "f"(f)); return u;
}
// RNA pre-bump: HMMA truncates low 13 bits; +0x1000 in stored bits -> RNA.
__device__ __forceinline__ float bumpf(float f) {
    return __uint_as_float(__float_as_uint(f) + 0x1000u);
}
__device__ __forceinline__ float ex2(float x) {
    float r; asm("ex2.approx.f32 %0,%1;" : "=f"(r) : "f"(x)); return r;
}

#define MMA_TF32(C0,C1,C2,C3, A0,A1,A2,A3, B0,B1) \
    asm("mma.sync.aligned.m16n8k8.row.col.f32.tf32.tf32.f32 " \
        "{%0,%1,%2,%3},{%4,%5,%6,%7},{%8,%9},{%0,%1,%2,%3};" \
        : "+f"(C0), "+f"(C1), "+f"(C2), "+f"(C3) \
        : "r"(A0), "r"(A1), "r"(A2), "r"(A3), "r"(B0), "r"(B1))

__device__ __forceinline__ void ldsm4(uint32_t& r0, uint32_t& r1,
                                      uint32_t& r2, uint32_t& r3, uint32_t addr) {
    asm volatile("ldmatrix.sync.aligned.m8n8.x4.shared.b16 {%0,%1,%2,%3},[%4];"
                 : "=r"(r0), "=r"(r1), "=r"(r2), "=r"(r3) : "r"(addr));
}

#define CP_ASYNC16(dst, src) \
    asm volatile("cp.async.cg.shared.global [%0],[%1],16;" :: "r"(dst), "l"(src))
#define CP_COMMIT() asm volatile("cp.async.commit_group;")
#define CP_WAITG(n) asm volatile("cp.async.wait_group %0;" :: "n"(n))

// Scratch (allocation-free rule: __device__ globals)
__device__ float g_qkv[(size_t)ROWS * QKV_N];   // bumped bits
__device__ float g_att[(size_t)ROWS * CDIM];    // bumped bits
__device__ float g_xb[(size_t)ROWS * CDIM];     // bumped x
__device__ float g_wqkvb[(size_t)QKV_N * CDIM]; // bumped Wqkv
__device__ float g_wprojb[(size_t)CDIM * CDIM]; // bumped Wproj

// ---------------------------------------------------------------------------
__global__ __launch_bounds__(256) void bump_kernel(
    const float4* __restrict__ src, float4* __restrict__ dst, int n4)
{
    const int i = blockIdx.x * 256 + threadIdx.x;
    if (i < n4) {
        float4 v = src[i];
        v.x = bumpf(v.x); v.y = bumpf(v.y); v.z = bumpf(v.z); v.w = bumpf(v.w);
        dst[i] = v;
    }
}

// ---------------------------------------------------------------------------
// tf32 tensor-core GEMM with bias (R13 2-stage, validated — unchanged).
// ---------------------------------------------------------------------------
#define TM 128
#define TN 128
#define TK 32
#define TILE_B (TM * TK * 4)
#define GEMM_SMEM (4 * TILE_B)

__global__ __launch_bounds__(256, 2) void gemm_tc_kernel(
    const float* __restrict__ A, const float* __restrict__ W,
    const float* __restrict__ bias, float* __restrict__ C,
    int M, int N, int K, int bumpOut)
{
    extern __shared__ char smem_raw[];
    const uint32_t sb  = (uint32_t)__cvta_generic_to_shared(smem_raw);
    const uint32_t Ab0 = sb;
    const uint32_t Bb0 = sb + 2 * TILE_B;

    const int t    = threadIdx.x;
    const int lane = t & 31;
    const int wid  = t >> 5;
    const int wm   = wid & 3;
    const int wn   = wid >> 2;
    const int m0   = blockIdx.y * TM;
    const int n0   = blockIdx.x * TN;
    const int mq   = lane >> 2;
    const int p    = lane & 3;

    const int rA    = wm * 32 + ((lane >> 3) & 1) * 8 + (lane & 7);
    const int halfA = (lane >> 4) & 1;
    const int xa    = rA & 7;
    const int rB    = wn * 64 + ((lane >> 4) & 1) * 8 + (lane & 7);
    const int halfB = (lane >> 3) & 1;
    const int xb    = rB & 7;

    const int lr = t >> 3;
    const int lc = t & 7;

    float c[2][8][4];
    #pragma unroll
    for (int i = 0; i < 2; i++)
        #pragma unroll
        for (int j = 0; j < 8; j++)
            #pragma unroll
            for (int r = 0; r < 4; r++) c[i][j][r] = 0.0f;

    const int nk = K / TK;

    #pragma unroll
    for (int i = 0; i < 4; i++) {
        const int r = lr + i * 32;
        const uint32_t sw = (uint32_t)((lc ^ (r & 7)) * 16);
        CP_ASYNC16(Ab0 + r * 128 + sw, (const char*)&A[(size_t)(m0 + r) * K + lc * 4]);
        CP_ASYNC16(Bb0 + r * 128 + sw, (const char*)&W[(size_t)(n0 + r) * K + lc * 4]);
    }
    CP_COMMIT();
    CP_WAITG(0);
    __syncthreads();

    int buf = 0;
    for (int kt = 0; kt < nk; kt++) {
        const bool more = (kt + 1 < nk);
        if (more) {
            const int ko = (kt + 1) * TK;
            const uint32_t Ad = Ab0 + (buf ^ 1) * TILE_B;
            const uint32_t Bd = Bb0 + (buf ^ 1) * TILE_B;
            #pragma unroll
            for (int i = 0; i < 4; i++) {
                const int r = lr + i * 32;
                const uint32_t sw = (uint32_t)((lc ^ (r & 7)) * 16);
                CP_ASYNC16(Ad + r * 128 + sw, (const char*)&A[(size_t)(m0 + r) * K + ko + lc * 4]);
                CP_ASYNC16(Bd + r * 128 + sw, (const char*)&W[(size_t)(n0 + r) * K + ko + lc * 4]);
            }
            CP_COMMIT();
        }

        const uint32_t Abase = Ab0 + buf * TILE_B;
        const uint32_t Bbase = Bb0 + buf * TILE_B;
        #pragma unroll
        for (int s = 0; s < 4; s++) {
            uint32_t af[2][4];
            #pragma unroll
            for (int mi = 0; mi < 2; mi++)
                ldsm4(af[mi][0], af[mi][1], af[mi][2], af[mi][3],
                      Abase + (rA + mi * 16) * 128 + ((uint32_t)(((2 * s + halfA) ^ xa) << 4)));
            uint32_t bf[8][2];
            #pragma unroll
            for (int g = 0; g < 4; g++) {
                uint32_t r0, r1, r2, r3;
                ldsm4(r0, r1, r2, r3,
                      Bbase + (rB + g * 16) * 128 + ((uint32_t)(((2 * s + halfB) ^ xb) << 4)));
                bf[2 * g][0] = r0; bf[2 * g][1] = r1;
                bf[2 * g + 1][0] = r2; bf[2 * g + 1][1] = r3;
            }
            #pragma unroll
            for (int mi = 0; mi < 2; mi++)
                #pragma unroll
                for (int ni = 0; ni < 8; ni++)
                    MMA_TF32(c[mi][ni][0], c[mi][ni][1], c[mi][ni][2], c[mi][ni][3],
                             af[mi][0], af[mi][1], af[mi][2], af[mi][3],
                             bf[ni][0], bf[ni][1]);
        }

        if (more) CP_WAITG(0);
        __syncthreads();
        buf ^= 1;
    }

    #pragma unroll
    for (int ni = 0; ni < 8; ni++) {
        const int n = n0 + wn * 64 + ni * 8 + p * 2;
        const float2 bb = *(const float2*)&bias[n];
        #pragma unroll
        for (int mi = 0; mi < 2; mi++) {
            const int mA = m0 + wm * 32 + mi * 16 + mq;
            float2 w0, w1;
            w0.x = c[mi][ni][0] + bb.x; w0.y = c[mi][ni][1] + bb.y;
            w1.x = c[mi][ni][2] + bb.x; w1.y = c[mi][ni][3] + bb.y;
            if (bumpOut) {
                w0.x = bumpf(w0.x); w0.y = bumpf(w0.y);
                w1.x = bumpf(w1.x); w1.y = bumpf(w1.y);
            }
            *(float2*)&C[(size_t)mA * N + n]       = w0;
            *(float2*)&C[(size_t)(mA + 8) * N + n] = w1;
        }
    }
}

// ---------------------------------------------------------------------------
// Tensor-core flash attention: single-term RNA QK, ex2 softmax,
// bias double-buffered in smem via cp.async (prefetched one tile ahead).
// K/V single smem buffer (double-buffering measured neutral in R12).
// smem: K 8K | V 8K | P 32K | bias 2x32K = 112 KB -> 2 CTAs/SM.
// ---------------------------------------------------------------------------
#define AQT 128
#define ABC 64
#define KS_OFF 0
#define VS_OFF 8192
#define PS_OFF 16384
#define BS_OFF(buf) (49152 + (buf) * 32768)
#define ATTN_SMEM 114688

__global__ __launch_bounds__(256, 2) void attn_tc_kernel(
    const float* __restrict__ qkv,   // [B*N, 2304] bumped bits
    const float* __restrict__ bias,  // [H, N, N]
    float* __restrict__ out)         // [B*N, 768]  written bumped
{
    extern __shared__ char asmem[];
    const uint32_t sb = (uint32_t)__cvta_generic_to_shared(asmem);

    const int t    = threadIdx.x;
    const int lane = t & 31;
    const int w    = t >> 5;
    const int b    = blockIdx.x >> 3;
    const int qb   = blockIdx.x & 7;
    const int h    = blockIdx.y;
    const int q0   = qb * AQT;
    const int mq   = lane >> 2;
    const int p    = lane & 3;

    const float qscale = 0.17677669529663687f * LOG2E;

    const int row_lo = w * 16 + mq;
    const int row_hi = row_lo + 8;

    const int bRow  = ((lane >> 4) & 1) * 8 + (lane & 7);
    const int bHalf = (lane >> 3) & 1;
    const int bx    = lane & 7;
    const int aRow  = w * 16 + ((lane >> 3) & 1) * 8 + (lane & 7);
    const int aHalf = (lane >> 4) & 1;
    const int ax    = aRow & 7;

    // K/V staging map: thread -> key row jL, chunks cLs / cLs+4
    const int jL  = t >> 2;
    const int cLs = t & 3;
    const float* kv0 = qkv + ((size_t)(b * SEQ + jL)) * QKV_N + h * 96;
    float4 kA = *(const float4*)(kv0 + 32 + cLs * 4);
    float4 kB = *(const float4*)(kv0 + 32 + cLs * 4 + 16);
    float4 vA = *(const float4*)(kv0 + 64 + cLs * 4);
    float4 vB = *(const float4*)(kv0 + 64 + cLs * 4 + 16);

    // bias staging map: thread -> row bR (0..127), 8 chunks of 16B
    const int bR = t >> 1;
    const int bC = (t & 1) * 8;          // chunk base (16 chunks per 256B row)
    const float* bsrc_row = bias + ((size_t)h * SEQ + q0 + bR) * SEQ;

    // ---- issue bias tile 0 ----
    {
        const uint32_t dstrow = sb + BS_OFF(0) + bR * 256;
        #pragma unroll
        for (int i = 0; i < 8; i++) {
            const int c = bC + i;
            CP_ASYNC16(dstrow + (uint32_t)((c ^ (bR & 7)) << 4),
                       (const char*)(bsrc_row + c * 4));
        }
        CP_COMMIT();
    }

    // ---- Q fragments: single-term RNA tf32, scaled by scale*log2e ----
    uint32_t qh[4][4];
    {
        const float* Qa = qkv + ((size_t)(b * SEQ + q0 + row_lo)) * QKV_N + h * 96;
        const float* Qb = qkv + ((size_t)(b * SEQ + q0 + row_hi)) * QKV_N + h * 96;
        #pragma unroll
        for (int s = 0; s < 4; s++) {
            qh[s][0] = f2tf(Qa[s * 8 + p]     * qscale);
            qh[s][1] = f2tf(Qb[s * 8 + p]     * qscale);
            qh[s][2] = f2tf(Qa[s * 8 + p + 4] * qscale);
            qh[s][3] = f2tf(Qb[s * 8 + p + 4] * qscale);
        }
    }

    float o[4][4];
    #pragma unroll
    for (int i = 0; i < 4; i++)
        #pragma unroll
        for (int j = 0; j < 4; j++) o[i][j] = 0.0f;
    float l_lo = 0.0f, l_hi = 0.0f;

    for (int kb = 0; kb < SEQ; kb += ABC) {
        const int bbuf  = (kb >> 6) & 1;
        const bool more = (kb + ABC < SEQ);

        // ---- store staged K/V regs -> smem (single buffer) ----
        *(float4*)(asmem + KS_OFF + jL * 128 + ((cLs       ^ (jL & 7)) << 4)) = kA;
        *(float4*)(asmem + KS_OFF + jL * 128 + (((cLs + 4) ^ (jL & 7)) << 4)) = kB;
        {
            const float vfA[4] = {vA.x, vA.y, vA.z, vA.w};
            const float vfB[4] = {vB.x, vB.y, vB.z, vB.w};
            #pragma unroll
            for (int e = 0; e < 4; e++) {
                const int d0 = cLs * 4 + e;
                const int d1 = d0 + 16;
                *(float*)(asmem + VS_OFF + d0 * 256 + (((jL >> 2) ^ (d0 & 7)) << 4) + ((jL & 3) << 2)) = vfA[e];
                *(float*)(asmem + VS_OFF + d1 * 256 + (((jL >> 2) ^ (d1 & 7)) << 4) + ((jL & 3) << 2)) = vfB[e];
            }
        }

        if (more) {
            // issue bias for kb+1 into other buffer
            const uint32_t dstrow = sb + BS_OFF(bbuf ^ 1) + bR * 256;
            const float* srow = bsrc_row + kb + ABC;
            #pragma unroll
            for (int i = 0; i < 8; i++) {
                const int c = bC + i;
                CP_ASYNC16(dstrow + (uint32_t)((c ^ (bR & 7)) << 4),
                           (const char*)(srow + c * 4));
            }
            CP_COMMIT();
            // prefetch next K/V into regs
            const float* nb = qkv + ((size_t)(b * SEQ + kb + ABC + jL)) * QKV_N + h * 96;
            kA = *(const float4*)(nb + 32 + cLs * 4);
            kB = *(const float4*)(nb + 32 + cLs * 4 + 16);
            vA = *(const float4*)(nb + 64 + cLs * 4);
            vB = *(const float4*)(nb + 64 + cLs * 4 + 16);
            CP_WAITG(1);   // bias(kb) resident, bias(kb+1) in flight
        } else {
            CP_WAITG(0);
        }
        __syncthreads();   // K/V + bias(kb) visible

        // ---- QK + exp2 + P, two j-tiles (16 keys) per group ----
        const uint32_t bsm = sb + BS_OFF(bbuf);
        #pragma unroll
        for (int g = 0; g < 4; g++) {
            float2 blo2[2], bhi2[2];
            #pragma unroll
            for (int u = 0; u < 2; u++) {
                const int ch = (2 * g + u) * 2 + (p >> 1);
                const uint32_t off = (uint32_t)(((ch ^ mq) << 4) + ((p & 1) << 3));
                blo2[u] = *(const float2*)(asmem + BS_OFF(bbuf) + row_lo * 256 + off);
                bhi2[u] = *(const float2*)(asmem + BS_OFF(bbuf) + row_hi * 256 + off);
            }

            float cf[2][4];
            #pragma unroll
            for (int u = 0; u < 2; u++)
                #pragma unroll
                for (int r = 0; r < 4; r++) cf[u][r] = 0.0f;

            #pragma unroll
            for (int s = 0; s < 4; s++) {
                uint32_t r0, r1, r2, r3;
                ldsm4(r0, r1, r2, r3,
                      sb + KS_OFF + (g * 16 + bRow) * 128 +
                      ((uint32_t)(((2 * s + bHalf) ^ bx) << 4)));
                MMA_TF32(cf[0][0], cf[0][1], cf[0][2], cf[0][3],
                         qh[s][0], qh[s][1], qh[s][2], qh[s][3], r0, r1);
                MMA_TF32(cf[1][0], cf[1][1], cf[1][2], cf[1][3],
                         qh[s][0], qh[s][1], qh[s][2], qh[s][3], r2, r3);
            }

            #pragma unroll
            for (int u = 0; u < 2; u++) {
                const int ni = 2 * g + u;
                const float p00 = ex2(fmaf(blo2[u].x, LOG2E, cf[u][0]));
                const float p01 = ex2(fmaf(blo2[u].y, LOG2E, cf[u][1]));
                const float p10 = ex2(fmaf(bhi2[u].x, LOG2E, cf[u][2]));
                const float p11 = ex2(fmaf(bhi2[u].y, LOG2E, cf[u][3]));
                l_lo += p00 + p01;
                l_hi += p10 + p11;
                const int c  = 2 * ni + (p >> 1);
                const int ob = (p & 1) << 3;
                *(float2*)(asmem + PS_OFF + row_lo * 256 + ((c ^ (row_lo & 7)) << 4) + ob)
                    = make_float2(bumpf(p00), bumpf(p01));
                *(float2*)(asmem + PS_OFF + row_hi * 256 + ((c ^ (row_hi & 7)) << 4) + ob)
                    = make_float2(bumpf(p10), bumpf(p11));
            }
        }
        __syncwarp();   // P rows are warp-private

        // ---- O += P V ----
        #pragma unroll
        for (int s2 = 0; s2 < 8; s2++) {
            uint32_t a0, a1, a2, a3;
            ldsm4(a0, a1, a2, a3,
                  sb + PS_OFF + aRow * 256 +
                  ((uint32_t)(((2 * s2 + aHalf) ^ ax) << 4)));
            #pragma unroll
            for (int grp = 0; grp < 2; grp++) {
                uint32_t v0, v1, v2, v3;
                ldsm4(v0, v1, v2, v3,
                      sb + VS_OFF + (grp * 16 + bRow) * 256 +
                      ((uint32_t)(((2 * s2 + bHalf) ^ bx) << 4)));
                MMA_TF32(o[grp * 2][0], o[grp * 2][1], o[grp * 2][2], o[grp * 2][3],
                         a0, a1, a2, a3, v0, v1);
                MMA_TF32(o[grp * 2 + 1][0], o[grp * 2 + 1][1],
                         o[grp * 2 + 1][2], o[grp * 2 + 1][3],
                         a0, a1, a2, a3, v2, v3);
            }
        }
        __syncthreads();   // all reads of K/V/P done before next overwrite
    }

    // ---- row-sum reduce across the 4 p-lanes of each row quad ----
    #pragma unroll
    for (int m = 1; m <= 2; m <<= 1) {
        l_lo += __shfl_xor_sync(0xffffffffu, l_lo, m);
        l_hi += __shfl_xor_sync(0xffffffffu, l_hi, m);
    }
    const float inv_lo = 1.0f / l_lo;
    const float inv_hi = 1.0f / l_hi;

    float* po_lo = out + ((size_t)(b * SEQ + q0 + row_lo)) * CDIM + h * DHEAD;
    float* po_hi = out + ((size_t)(b * SEQ + q0 + row_hi)) * CDIM + h * DHEAD;
    #pragma unroll
    for (int nt = 0; nt < 4; nt++) {
        float2 w0, w1;
        w0.x = bumpf(o[nt][0] * inv_lo); w0.y = bumpf(o[nt][1] * inv_lo);
        w1.x = bumpf(o[nt][2] * inv_hi); w1.y = bumpf(o[nt][3] * inv_hi);
        *(float2*)(po_lo + nt * 8 + 2 * p) = w0;
        *(float2*)(po_hi + nt * 8 + 2 * p) = w1;
    }
}

// ---------------------------------------------------------------------------
extern "C" void kernel_launch(void* const* d_in, const int* in_sizes, int n_in,
                              void* d_out, int out_size)
{
    const float* x      = (const float*)d_in[0];
    const float* relpos = (const float*)d_in[1];
    const float* Wqkv   = (const float*)d_in[2];
    const float* bqkv   = (const float*)d_in[3];
    const float* Wproj  = (const float*)d_in[4];
    const float* bproj  = (const float*)d_in[5];
    float* out = (float*)d_out;

    float *qkv, *att, *xb, *wqkvb, *wprojb;
    cudaGetSymbolAddress((void**)&qkv, g_qkv);
    cudaGetSymbolAddress((void**)&att, g_att);
    cudaGetSymbolAddress((void**)&xb, g_xb);
    cudaGetSymbolAddress((void**)&wqkvb, g_wqkvb);
    cudaGetSymbolAddress((void**)&wprojb, g_wprojb);

    cudaFuncSetAttribute(gemm_tc_kernel,
                         cudaFuncAttributeMaxDynamicSharedMemorySize, GEMM_SMEM);
    cudaFuncSetAttribute(attn_tc_kernel,
                         cudaFuncAttributeMaxDynamicSharedMemorySize, ATTN_SMEM);

    // 0) pre-bump inputs
    bump_kernel<<<(ROWS * CDIM / 4 + 255) / 256, 256>>>(
        (const float4*)x, (float4*)xb, ROWS * CDIM / 4);
    bump_kernel<<<(QKV_N * CDIM / 4 + 255) / 256, 256>>>(
        (const float4*)Wqkv, (float4*)wqkvb, QKV_N * CDIM / 4);
    bump_kernel<<<(CDIM * CDIM / 4 + 255) / 256, 256>>>(
        (const float4*)Wproj, (float4*)wprojb, CDIM * CDIM / 4);

    // 1) QKV projection (stores bumped bits)
    gemm_tc_kernel<<<dim3(QKV_N / TN, ROWS / TM), 256, GEMM_SMEM>>>(
        xb, wqkvb, bqkv, qkv, ROWS, QKV_N, CDIM, 1);

    // 2) tensor-core flash attention (stores bumped bits)
    attn_tc_kernel<<<dim3(BATCH * (SEQ / AQT), HEADS), 256, ATTN_SMEM>>>(
        qkv, relpos, att);

    // 3) output projection (exact store)
    gemm_tc_kernel<<<dim3(CDIM / TN, ROWS / TM), 256, GEMM_SMEM>>>(
        att, wprojb, bproj, out, ROWS, CDIM, CDIM, 0);
}

// round 16
// speedup vs baseline: 1.1915x; 1.1915x over previous
#include <cuda_runtime.h>
#include <cuda_bf16.h>
#include <cstddef>
#include <cstdint>

// Problem constants
#define BATCH 8
#define SEQ   1024
#define CDIM  768
#define HEADS 24
#define DHEAD 32
#define QKV_N (3*CDIM)          // 2304
#define ROWS  (BATCH*SEQ)       // 8192

#define LOG2E 1.4426950408889634f

__device__ __forceinline__ uint32_t f2tf(float f) {
    uint32_t u; asm("cvt.rna.tf32.f32 %0,%1;" : "=r"(u) : "f"(f)); return u;
}
// RNA pre-bump: HMMA truncates low 13 bits; +0x1000 in stored bits -> RNA.
__device__ __forceinline__ float bumpf(float f) {
    return __uint_as_float(__float_as_uint(f) + 0x1000u);
}
__device__ __forceinline__ float ex2(float x) {
    float r; asm("ex2.approx.f32 %0,%1;" : "=f"(r) : "f"(x)); return r;
}

#define MMA_TF32(C0,C1,C2,C3, A0,A1,A2,A3, B0,B1) \
    asm("mma.sync.aligned.m16n8k8.row.col.f32.tf32.tf32.f32 " \
        "{%0,%1,%2,%3},{%4,%5,%6,%7},{%8,%9},{%0,%1,%2,%3};" \
        : "+f"(C0), "+f"(C1), "+f"(C2), "+f"(C3) \
        : "r"(A0), "r"(A1), "r"(A2), "r"(A3), "r"(B0), "r"(B1))

__device__ __forceinline__ void ldsm4(uint32_t& r0, uint32_t& r1,
                                      uint32_t& r2, uint32_t& r3, uint32_t addr) {
    asm volatile("ldmatrix.sync.aligned.m8n8.x4.shared.b16 {%0,%1,%2,%3},[%4];"
                 : "=r"(r0), "=r"(r1), "=r"(r2), "=r"(r3) : "r"(addr));
}

#define CP_ASYNC16(dst, src) \
    asm volatile("cp.async.cg.shared.global [%0],[%1],16;" :: "r"(dst), "l"(src))
#define CP_COMMIT() asm volatile("cp.async.commit_group;")
#define CP_WAITG(n) asm volatile("cp.async.wait_group %0;" :: "n"(n))

// Scratch (allocation-free rule: __device__ globals)
__device__ float g_qkv[(size_t)ROWS * QKV_N];   // bumped bits
__device__ float g_att[(size_t)ROWS * CDIM];    // bumped bits
__device__ float g_xb[(size_t)ROWS * CDIM];     // bumped x
__device__ float g_wqkvb[(size_t)QKV_N * CDIM]; // bumped Wqkv
__device__ float g_wprojb[(size_t)CDIM * CDIM]; // bumped Wproj

// ---------------------------------------------------------------------------
__global__ __launch_bounds__(256) void bump_kernel(
    const float4* __restrict__ src, float4* __restrict__ dst, int n4)
{
    const int i = blockIdx.x * 256 + threadIdx.x;
    if (i < n4) {
        float4 v = src[i];
        v.x = bumpf(v.x); v.y = bumpf(v.y); v.z = bumpf(v.z); v.w = bumpf(v.w);
        dst[i] = v;
    }
}

// ---------------------------------------------------------------------------
// tf32 tensor-core GEMM with bias (R13 2-stage, validated — unchanged).
// ---------------------------------------------------------------------------
#define TM 128
#define TN 128
#define TK 32
#define TILE_B (TM * TK * 4)
#define GEMM_SMEM (4 * TILE_B)

__global__ __launch_bounds__(256, 2) void gemm_tc_kernel(
    const float* __restrict__ A, const float* __restrict__ W,
    const float* __restrict__ bias, float* __restrict__ C,
    int M, int N, int K, int bumpOut)
{
    extern __shared__ char smem_raw[];
    const uint32_t sb  = (uint32_t)__cvta_generic_to_shared(smem_raw);
    const uint32_t Ab0 = sb;
    const uint32_t Bb0 = sb + 2 * TILE_B;

    const int t    = threadIdx.x;
    const int lane = t & 31;
    const int wid  = t >> 5;
    const int wm   = wid & 3;
    const int wn   = wid >> 2;
    const int m0   = blockIdx.y * TM;
    const int n0   = blockIdx.x * TN;
    const int mq   = lane >> 2;
    const int p    = lane & 3;

    const int rA    = wm * 32 + ((lane >> 3) & 1) * 8 + (lane & 7);
    const int halfA = (lane >> 4) & 1;
    const int xa    = rA & 7;
    const int rB    = wn * 64 + ((lane >> 4) & 1) * 8 + (lane & 7);
    const int halfB = (lane >> 3) & 1;
    const int xb    = rB & 7;

    const int lr = t >> 3;
    const int lc = t & 7;

    float c[2][8][4];
    #pragma unroll
    for (int i = 0; i < 2; i++)
        #pragma unroll
        for (int j = 0; j < 8; j++)
            #pragma unroll
            for (int r = 0; r < 4; r++) c[i][j][r] = 0.0f;

    const int nk = K / TK;

    #pragma unroll
    for (int i = 0; i < 4; i++) {
        const int r = lr + i * 32;
        const uint32_t sw = (uint32_t)((lc ^ (r & 7)) * 16);
        CP_ASYNC16(Ab0 + r * 128 + sw, (const char*)&A[(size_t)(m0 + r) * K + lc * 4]);
        CP_ASYNC16(Bb0 + r * 128 + sw, (const char*)&W[(size_t)(n0 + r) * K + lc * 4]);
    }
    CP_COMMIT();
    CP_WAITG(0);
    __syncthreads();

    int buf = 0;
    for (int kt = 0; kt < nk; kt++) {
        const bool more = (kt + 1 < nk);
        if (more) {
            const int ko = (kt + 1) * TK;
            const uint32_t Ad = Ab0 + (buf ^ 1) * TILE_B;
            const uint32_t Bd = Bb0 + (buf ^ 1) * TILE_B;
            #pragma unroll
            for (int i = 0; i < 4; i++) {
                const int r = lr + i * 32;
                const uint32_t sw = (uint32_t)((lc ^ (r & 7)) * 16);
                CP_ASYNC16(Ad + r * 128 + sw, (const char*)&A[(size_t)(m0 + r) * K + ko + lc * 4]);
                CP_ASYNC16(Bd + r * 128 + sw, (const char*)&W[(size_t)(n0 + r) * K + ko + lc * 4]);
            }
            CP_COMMIT();
        }

        const uint32_t Abase = Ab0 + buf * TILE_B;
        const uint32_t Bbase = Bb0 + buf * TILE_B;
        #pragma unroll
        for (int s = 0; s < 4; s++) {
            uint32_t af[2][4];
            #pragma unroll
            for (int mi = 0; mi < 2; mi++)
                ldsm4(af[mi][0], af[mi][1], af[mi][2], af[mi][3],
                      Abase + (rA + mi * 16) * 128 + ((uint32_t)(((2 * s + halfA) ^ xa) << 4)));
            uint32_t bf[8][2];
            #pragma unroll
            for (int g = 0; g < 4; g++) {
                uint32_t r0, r1, r2, r3;
                ldsm4(r0, r1, r2, r3,
                      Bbase + (rB + g * 16) * 128 + ((uint32_t)(((2 * s + halfB) ^ xb) << 4)));
                bf[2 * g][0] = r0; bf[2 * g][1] = r1;
                bf[2 * g + 1][0] = r2; bf[2 * g + 1][1] = r3;
            }
            #pragma unroll
            for (int mi = 0; mi < 2; mi++)
                #pragma unroll
                for (int ni = 0; ni < 8; ni++)
                    MMA_TF32(c[mi][ni][0], c[mi][ni][1], c[mi][ni][2], c[mi][ni][3],
                             af[mi][0], af[mi][1], af[mi][2], af[mi][3],
                             bf[ni][0], bf[ni][1]);
        }

        if (more) CP_WAITG(0);
        __syncthreads();
        buf ^= 1;
    }

    #pragma unroll
    for (int ni = 0; ni < 8; ni++) {
        const int n = n0 + wn * 64 + ni * 8 + p * 2;
        const float2 bb = *(const float2*)&bias[n];
        #pragma unroll
        for (int mi = 0; mi < 2; mi++) {
            const int mA = m0 + wm * 32 + mi * 16 + mq;
            float2 w0, w1;
            w0.x = c[mi][ni][0] + bb.x; w0.y = c[mi][ni][1] + bb.y;
            w1.x = c[mi][ni][2] + bb.x; w1.y = c[mi][ni][3] + bb.y;
            if (bumpOut) {
                w0.x = bumpf(w0.x); w0.y = bumpf(w0.y);
                w1.x = bumpf(w1.x); w1.y = bumpf(w1.y);
            }
            *(float2*)&C[(size_t)mA * N + n]       = w0;
            *(float2*)&C[(size_t)(mA + 8) * N + n] = w1;
        }
    }
}

// ---------------------------------------------------------------------------
// Tensor-core flash attention (R13 structure) + bias register pipeline:
// group g+1's bias LDGs issued before group g's MMA chain.
// ---------------------------------------------------------------------------
#define AQT 128
#define ABC 64
#define KS_OFF(buf) ((buf) * 8192)
#define VS_OFF(buf) (16384 + (buf) * 8192)
#define PS_OFF 32768
#define ATTN_SMEM 65536

__global__ __launch_bounds__(256, 2) void attn_tc_kernel(
    const float* __restrict__ qkv,   // [B*N, 2304] bumped bits
    const float* __restrict__ bias,  // [H, N, N]
    float* __restrict__ out)         // [B*N, 768]  written bumped
{
    extern __shared__ char asmem[];
    const uint32_t sb = (uint32_t)__cvta_generic_to_shared(asmem);

    const int t    = threadIdx.x;
    const int lane = t & 31;
    const int w    = t >> 5;
    const int b    = blockIdx.x >> 3;
    const int qb   = blockIdx.x & 7;
    const int h    = blockIdx.y;
    const int q0   = qb * AQT;
    const int mq   = lane >> 2;
    const int p    = lane & 3;

    const float qscale = 0.17677669529663687f * LOG2E;

    const int row_lo = w * 16 + mq;
    const int row_hi = row_lo + 8;

    const int bRow  = ((lane >> 4) & 1) * 8 + (lane & 7);
    const int bHalf = (lane >> 3) & 1;
    const int bx    = lane & 7;
    const int aRow  = w * 16 + ((lane >> 3) & 1) * 8 + (lane & 7);
    const int aHalf = (lane >> 4) & 1;
    const int ax    = aRow & 7;

    const int jL  = t >> 2;
    const int cLs = t & 3;
    const float* kv0 = qkv + ((size_t)(b * SEQ + jL)) * QKV_N + h * 96;
    float4 kA = *(const float4*)(kv0 + 32 + cLs * 4);
    float4 kB = *(const float4*)(kv0 + 32 + cLs * 4 + 16);
    float4 vA = *(const float4*)(kv0 + 64 + cLs * 4);
    float4 vB = *(const float4*)(kv0 + 64 + cLs * 4 + 16);

    // ---- Q fragments: single-term RNA tf32, scaled by scale*log2e ----
    uint32_t qh[4][4];
    {
        const float* Qa = qkv + ((size_t)(b * SEQ + q0 + row_lo)) * QKV_N + h * 96;
        const float* Qb = qkv + ((size_t)(b * SEQ + q0 + row_hi)) * QKV_N + h * 96;
        #pragma unroll
        for (int s = 0; s < 4; s++) {
            qh[s][0] = f2tf(Qa[s * 8 + p]     * qscale);
            qh[s][1] = f2tf(Qb[s * 8 + p]     * qscale);
            qh[s][2] = f2tf(Qa[s * 8 + p + 4] * qscale);
            qh[s][3] = f2tf(Qb[s * 8 + p + 4] * qscale);
        }
    }

    const float* bp_lo = bias + ((size_t)h * SEQ + q0 + row_lo) * SEQ + 2 * p;
    const float* bp_hi = bias + ((size_t)h * SEQ + q0 + row_hi) * SEQ + 2 * p;

    float o[4][4];
    #pragma unroll
    for (int i = 0; i < 4; i++)
        #pragma unroll
        for (int j = 0; j < 4; j++) o[i][j] = 0.0f;
    float l_lo = 0.0f, l_hi = 0.0f;

    // ---- stage tile 0 into buffer 0 ----
    {
        *(float4*)(asmem + KS_OFF(0) + jL * 128 + ((cLs       ^ (jL & 7)) << 4)) = kA;
        *(float4*)(asmem + KS_OFF(0) + jL * 128 + (((cLs + 4) ^ (jL & 7)) << 4)) = kB;
        const float vfA[4] = {vA.x, vA.y, vA.z, vA.w};
        const float vfB[4] = {vB.x, vB.y, vB.z, vB.w};
        #pragma unroll
        for (int e = 0; e < 4; e++) {
            const int d0 = cLs * 4 + e;
            const int d1 = d0 + 16;
            *(float*)(asmem + VS_OFF(0) + d0 * 256 + (((jL >> 2) ^ (d0 & 7)) << 4) + ((jL & 3) << 2)) = vfA[e];
            *(float*)(asmem + VS_OFF(0) + d1 * 256 + (((jL >> 2) ^ (d1 & 7)) << 4) + ((jL & 3) << 2)) = vfB[e];
        }
    }
    __syncthreads();

    for (int kb = 0; kb < SEQ; kb += ABC) {
        const int buf   = (kb >> 6) & 1;
        const bool more = (kb + ABC < SEQ);

        if (more) {
            const float* nb = qkv + ((size_t)(b * SEQ + kb + ABC + jL)) * QKV_N + h * 96;
            kA = *(const float4*)(nb + 32 + cLs * 4);
            kB = *(const float4*)(nb + 32 + cLs * 4 + 16);
            vA = *(const float4*)(nb + 64 + cLs * 4);
            vB = *(const float4*)(nb + 64 + cLs * 4 + 16);
        }

        // ---- bias register pipeline: preload group 0 ----
        float2 blo2[2][2], bhi2[2][2];
        #pragma unroll
        for (int u = 0; u < 2; u++) {
            blo2[0][u] = *(const float2*)(bp_lo + kb + u * 8);
            bhi2[0][u] = *(const float2*)(bp_hi + kb + u * 8);
        }

        // ---- QK + exp2 + P, two j-tiles (16 keys) per group ----
        #pragma unroll
        for (int g = 0; g < 4; g++) {
            // prefetch next group's bias before this group's MMA chain
            if (g < 3) {
                #pragma unroll
                for (int u = 0; u < 2; u++) {
                    const int jj = kb + (2 * (g + 1) + u) * 8;
                    blo2[(g + 1) & 1][u] = *(const float2*)(bp_lo + jj);
                    bhi2[(g + 1) & 1][u] = *(const float2*)(bp_hi + jj);
                }
            }

            float cf[2][4];
            #pragma unroll
            for (int u = 0; u < 2; u++)
                #pragma unroll
                for (int r = 0; r < 4; r++) cf[u][r] = 0.0f;

            #pragma unroll
            for (int s = 0; s < 4; s++) {
                uint32_t r0, r1, r2, r3;
                ldsm4(r0, r1, r2, r3,
                      sb + KS_OFF(buf) + (g * 16 + bRow) * 128 +
                      ((uint32_t)(((2 * s + bHalf) ^ bx) << 4)));
                MMA_TF32(cf[0][0], cf[0][1], cf[0][2], cf[0][3],
                         qh[s][0], qh[s][1], qh[s][2], qh[s][3], r0, r1);
                MMA_TF32(cf[1][0], cf[1][1], cf[1][2], cf[1][3],
                         qh[s][0], qh[s][1], qh[s][2], qh[s][3], r2, r3);
            }

            #pragma unroll
            for (int u = 0; u < 2; u++) {
                const int ni = 2 * g + u;
                const float p00 = ex2(fmaf(blo2[g & 1][u].x, LOG2E, cf[u][0]));
                const float p01 = ex2(fmaf(blo2[g & 1][u].y, LOG2E, cf[u][1]));
                const float p10 = ex2(fmaf(bhi2[g & 1][u].x, LOG2E, cf[u][2]));
                const float p11 = ex2(fmaf(bhi2[g & 1][u].y, LOG2E, cf[u][3]));
                l_lo += p00 + p01;
                l_hi += p10 + p11;
                const int c  = 2 * ni + (p >> 1);
                const int ob = (p & 1) << 3;
                *(float2*)(asmem + PS_OFF + row_lo * 256 + ((c ^ (row_lo & 7)) << 4) + ob)
                    = make_float2(bumpf(p00), bumpf(p01));
                *(float2*)(asmem + PS_OFF + row_hi * 256 + ((c ^ (row_hi & 7)) << 4) + ob)
                    = make_float2(bumpf(p10), bumpf(p11));
            }
        }
        __syncwarp();   // P rows are warp-private

        // ---- O += P V ----
        #pragma unroll
        for (int s2 = 0; s2 < 8; s2++) {
            uint32_t a0, a1, a2, a3;
            ldsm4(a0, a1, a2, a3,
                  sb + PS_OFF + aRow * 256 +
                  ((uint32_t)(((2 * s2 + aHalf) ^ ax) << 4)));
            #pragma unroll
            for (int grp = 0; grp < 2; grp++) {
                uint32_t v0, v1, v2, v3;
                ldsm4(v0, v1, v2, v3,
                      sb + VS_OFF(buf) + (grp * 16 + bRow) * 256 +
                      ((uint32_t)(((2 * s2 + bHalf) ^ bx) << 4)));
                MMA_TF32(o[grp * 2][0], o[grp * 2][1], o[grp * 2][2], o[grp * 2][3],
                         a0, a1, a2, a3, v0, v1);
                MMA_TF32(o[grp * 2 + 1][0], o[grp * 2 + 1][1],
                         o[grp * 2 + 1][2], o[grp * 2 + 1][3],
                         a0, a1, a2, a3, v2, v3);
            }
        }

        // ---- stage next tile into the other buffer ----
        if (more) {
            const int nb2 = buf ^ 1;
            *(float4*)(asmem + KS_OFF(nb2) + jL * 128 + ((cLs       ^ (jL & 7)) << 4)) = kA;
            *(float4*)(asmem + KS_OFF(nb2) + jL * 128 + (((cLs + 4) ^ (jL & 7)) << 4)) = kB;
            const float vfA[4] = {vA.x, vA.y, vA.z, vA.w};
            const float vfB[4] = {vB.x, vB.y, vB.z, vB.w};
            #pragma unroll
            for (int e = 0; e < 4; e++) {
                const int d0 = cLs * 4 + e;
                const int d1 = d0 + 16;
                *(float*)(asmem + VS_OFF(nb2) + d0 * 256 + (((jL >> 2) ^ (d0 & 7)) << 4) + ((jL & 3) << 2)) = vfA[e];
                *(float*)(asmem + VS_OFF(nb2) + d1 * 256 + (((jL >> 2) ^ (d1 & 7)) << 4) + ((jL & 3) << 2)) = vfB[e];
            }
        }
        __syncthreads();
    }

    // ---- row-sum reduce across the 4 p-lanes of each row quad ----
    #pragma unroll
    for (int m = 1; m <= 2; m <<= 1) {
        l_lo += __shfl_xor_sync(0xffffffffu, l_lo, m);
        l_hi += __shfl_xor_sync(0xffffffffu, l_hi, m);
    }
    const float inv_lo = 1.0f / l_lo;
    const float inv_hi = 1.0f / l_hi;

    float* po_lo = out + ((size_t)(b * SEQ + q0 + row_lo)) * CDIM + h * DHEAD;
    float* po_hi = out + ((size_t)(b * SEQ + q0 + row_hi)) * CDIM + h * DHEAD;
    #pragma unroll
    for (int nt = 0; nt < 4; nt++) {
        float2 w0, w1;
        w0.x = bumpf(o[nt][0] * inv_lo); w0.y = bumpf(o[nt][1] * inv_lo);
        w1.x = bumpf(o[nt][2] * inv_hi); w1.y = bumpf(o[nt][3] * inv_hi);
        *(float2*)(po_lo + nt * 8 + 2 * p) = w0;
        *(float2*)(po_hi + nt * 8 + 2 * p) = w1;
    }
}

// ---------------------------------------------------------------------------
extern "C" void kernel_launch(void* const* d_in, const int* in_sizes, int n_in,
                              void* d_out, int out_size)
{
    const float* x      = (const float*)d_in[0];
    const float* relpos = (const float*)d_in[1];
    const float* Wqkv   = (const float*)d_in[2];
    const float* bqkv   = (const float*)d_in[3];
    const float* Wproj  = (const float*)d_in[4];
    const float* bproj  = (const float*)d_in[5];
    float* out = (float*)d_out;

    float *qkv, *att, *xb, *wqkvb, *wprojb;
    cudaGetSymbolAddress((void**)&qkv, g_qkv);
    cudaGetSymbolAddress((void**)&att, g_att);
    cudaGetSymbolAddress((void**)&xb, g_xb);
    cudaGetSymbolAddress((void**)&wqkvb, g_wqkvb);
    cudaGetSymbolAddress((void**)&wprojb, g_wprojb);

    cudaFuncSetAttribute(gemm_tc_kernel,
                         cudaFuncAttributeMaxDynamicSharedMemorySize, GEMM_SMEM);
    cudaFuncSetAttribute(attn_tc_kernel,
                         cudaFuncAttributeMaxDynamicSharedMemorySize, ATTN_SMEM);

    // 0) pre-bump inputs
    bump_kernel<<<(ROWS * CDIM / 4 + 255) / 256, 256>>>(
        (const float4*)x, (float4*)xb, ROWS * CDIM / 4);
    bump_kernel<<<(QKV_N * CDIM / 4 + 255) / 256, 256>>>(
        (const float4*)Wqkv, (float4*)wqkvb, QKV_N * CDIM / 4);
    bump_kernel<<<(CDIM * CDIM / 4 + 255) / 256, 256>>>(
        (const float4*)Wproj, (float4*)wprojb, CDIM * CDIM / 4);

    // 1) QKV projection (stores bumped bits)
    gemm_tc_kernel<<<dim3(QKV_N / TN, ROWS / TM), 256, GEMM_SMEM>>>(
        xb, wqkvb, bqkv, qkv, ROWS, QKV_N, CDIM, 1);

    // 2) tensor-core flash attention (stores bumped bits)
    attn_tc_kernel<<<dim3(BATCH * (SEQ / AQT), HEADS), 256, ATTN_SMEM>>>(
        qkv, relpos, att);

    // 3) output projection (exact store)
    gemm_tc_kernel<<<dim3(CDIM / TN, ROWS / TM), 256, GEMM_SMEM>>>(
        att, wprojb, bproj, out, ROWS, CDIM, CDIM, 0);
}